// round 1
// baseline (speedup 1.0000x reference)
#include <cuda_runtime.h>
#include <cstdint>
#include <cstddef>

#define BB 4
#define NN 4096
#define MM 1024
#define CC 128
#define DD 256
#define PHD 64
#define AHD 512
#define KNB 16
#define RR (BB*NN*KNB)   // 262144 rows (b,n,k)

// ---------------- static scratch (allocation-free rule: __device__ globals) ----
__device__ float g_value[BB*DD*MM];            // (B,D,M)
__device__ float g_keyf [BB*DD*MM];            // (B,D,M)
__device__ float g_valft[BB*MM*DD];            // (B,M,D)  transposed for coalesced gather
__device__ float g_query[BB*DD*NN];            // (B,D,N)
__device__ float g_W1qt [BB*NN*AHD];           // (B,N,AH) = (attn_w1 @ query)^T
__device__ float g_W1kt [BB*MM*AHD];           // (B,M,AH) = (attn_w1 @ key_f)^T
__device__ int   g_idx  [RR];                  // (B,N,K)
__device__ float g_hreluT[PHD*RR];             // (PH, R) channel-major
__device__ float g_hid  [134217728];           // (R, AH) row-major   512 MB
__device__ float g_logits[67108864];           // (R, D)  row-major   256 MB
__device__ float g_pe   [67108864];            // (R, D)  row-major   256 MB
__device__ float g_agg  [BB*NN*DD];            // (B*N, D) row-major
__device__ float g_pre1 [AHD*PHD];             // attn_w1 @ pos_w2  (512,64)
__device__ float g_aA[AHD], g_cA[AHD], g_aP[PHD], g_cP[PHD];

// ---------------- precompute: pre1 = W1@pos_w2, folded BN constants -----------
__global__ void precomp_kernel(const float* __restrict__ w1,      // (512,256)
                               const float* __restrict__ pw2,     // (256,64)
                               const float* __restrict__ pb2,     // (256)
                               const float* __restrict__ ag, const float* __restrict__ abeta,
                               const float* __restrict__ amu, const float* __restrict__ avar,
                               const float* __restrict__ ab1,
                               const float* __restrict__ pg, const float* __restrict__ pbeta,
                               const float* __restrict__ pmu, const float* __restrict__ pvar,
                               const float* __restrict__ pb1,
                               float* __restrict__ pre1, float* __restrict__ aA,
                               float* __restrict__ cA, float* __restrict__ aP,
                               float* __restrict__ cP)
{
    int o = blockIdx.x;
    if (o < AHD) {
        int p = threadIdx.x;  // 64
        float s = 0.f;
        for (int c = 0; c < DD; c++) s += w1[o*DD + c] * pw2[c*PHD + p];
        pre1[o*PHD + p] = s;
        if (p == 0) {
            float vb = 0.f;
            for (int c = 0; c < DD; c++) vb += w1[o*DD + c] * pb2[c];
            float inv = ag[o] / sqrtf(avar[o] + 1e-5f);
            aA[o] = inv;
            cA[o] = (ab1[o] - amu[o]) * inv + abeta[o] + vb * inv;
        }
    } else {
        int p = threadIdx.x;
        float inv = pg[p] / sqrtf(pvar[p] + 1e-5f);
        aP[p] = inv;
        cP[p] = (pb1[p] - pmu[p]) * inv + pbeta[p];
    }
}

// ---------------- generic fp32 tiled GEMM: C = W(O,K) * A + bias (+resid) -----
// A layout: A_RM ? (b, X, K) row-major  :  (b, K, X) channel-major
// C layout: OUT_XO ? (b, X, O)          :  (b, O, X)
constexpr int TBO = 128, TBX = 128, TBK = 16;

template<bool A_RM, bool OUT_XO>
__global__ __launch_bounds__(256)
void gemm_k(const float* __restrict__ W, const float* __restrict__ bias,
            const float* __restrict__ A, const float* __restrict__ resid,
            float* __restrict__ C, int O, int K, int X, size_t sA, size_t sC)
{
    __shared__ float As[TBK][TBX];
    __shared__ float Ws[TBK][TBO];
    const int bx = blockIdx.x * TBX;
    const int bo = blockIdx.y * TBO;
    const int b  = blockIdx.z;
    const float* Ab = A + (size_t)b * sA;
    float* Cb = C + (size_t)b * sC;
    const int tid = threadIdx.x;
    const int tco = (tid & 15) * 4;   // o micro-base (two halves: +0, +64)
    const int tcx = (tid >> 4) * 4;   // x micro-base (two halves: +0, +64)

    float acc[8][8];
#pragma unroll
    for (int i = 0; i < 8; i++)
#pragma unroll
        for (int j = 0; j < 8; j++) acc[i][j] = 0.f;

    for (int k0 = 0; k0 < K; k0 += TBK) {
        if (A_RM) {
            int row = tid >> 1, c0 = (tid & 1) * 8;
            const float* p = Ab + (size_t)(bx + row) * K + k0 + c0;
            float4 v0 = *(const float4*)p;
            float4 v1 = *(const float4*)(p + 4);
            As[c0+0][row] = v0.x; As[c0+1][row] = v0.y;
            As[c0+2][row] = v0.z; As[c0+3][row] = v0.w;
            As[c0+4][row] = v1.x; As[c0+5][row] = v1.y;
            As[c0+6][row] = v1.z; As[c0+7][row] = v1.w;
        } else {
            int kk = tid >> 4, x8 = (tid & 15) * 8;
            const float* p = Ab + (size_t)(k0 + kk) * X + bx + x8;
            float4 v0 = *(const float4*)p;
            float4 v1 = *(const float4*)(p + 4);
            *(float4*)&As[kk][x8]     = v0;
            *(float4*)&As[kk][x8 + 4] = v1;
        }
        {
            int row = tid >> 1, c0 = (tid & 1) * 8;
            const float* p = W + (size_t)(bo + row) * K + k0 + c0;
            float4 v0 = *(const float4*)p;
            float4 v1 = *(const float4*)(p + 4);
            Ws[c0+0][row] = v0.x; Ws[c0+1][row] = v0.y;
            Ws[c0+2][row] = v0.z; Ws[c0+3][row] = v0.w;
            Ws[c0+4][row] = v1.x; Ws[c0+5][row] = v1.y;
            Ws[c0+6][row] = v1.z; Ws[c0+7][row] = v1.w;
        }
        __syncthreads();
#pragma unroll
        for (int kk = 0; kk < TBK; kk++) {
            float4 a0 = *(const float4*)&As[kk][tcx];
            float4 a1 = *(const float4*)&As[kk][tcx + 64];
            float4 w0 = *(const float4*)&Ws[kk][tco];
            float4 w1 = *(const float4*)&Ws[kk][tco + 64];
            float a[8] = {a0.x, a0.y, a0.z, a0.w, a1.x, a1.y, a1.z, a1.w};
            float w[8] = {w0.x, w0.y, w0.z, w0.w, w1.x, w1.y, w1.z, w1.w};
#pragma unroll
            for (int i = 0; i < 8; i++)
#pragma unroll
                for (int j = 0; j < 8; j++)
                    acc[i][j] = fmaf(a[i], w[j], acc[i][j]);
        }
        __syncthreads();
    }
    // epilogue
#pragma unroll
    for (int i = 0; i < 8; i++) {
        int xx = bx + (i < 4 ? tcx + i : 64 + tcx + (i - 4));
#pragma unroll
        for (int jh = 0; jh < 2; jh++) {
            int oo = bo + tco + jh * 64;
            float vr[4];
#pragma unroll
            for (int j = 0; j < 4; j++) vr[j] = acc[i][jh * 4 + j];
            if (bias) {
#pragma unroll
                for (int j = 0; j < 4; j++) vr[j] += bias[oo + j];
            }
            if (OUT_XO) {
                size_t ix = (size_t)xx * O + oo;
                if (resid) {
                    float4 rv = *(const float4*)(resid + (size_t)b * sC + ix);
                    vr[0] += rv.x; vr[1] += rv.y; vr[2] += rv.z; vr[3] += rv.w;
                }
                float4 ov = {vr[0], vr[1], vr[2], vr[3]};
                *(float4*)(Cb + ix) = ov;
            } else {
#pragma unroll
                for (int j = 0; j < 4; j++) {
                    size_t ix = (size_t)(oo + j) * X + xx;
                    float v = vr[j];
                    if (resid) v += resid[(size_t)b * sC + ix];
                    Cb[ix] = v;
                }
            }
        }
    }
}

// ---------------- KNN: warp per query point, expanded-form distances ----------
__global__ __launch_bounds__(128)
void knn_kernel(const float* __restrict__ pf,    // (B,N,3)
                const float* __restrict__ seed,  // (B,M,3)
                int* __restrict__ idx_out)       // (B,N,16)
{
    __shared__ float sx[MM], sy[MM], sz[MM], ss[MM];
    __shared__ float sd[4][MM];
    int b = blockIdx.y;
    const float* sb = seed + (size_t)b * MM * 3;
    for (int j = threadIdx.x; j < MM; j += 128) {
        float x = sb[j*3], y = sb[j*3+1], z = sb[j*3+2];
        sx[j] = x; sy[j] = y; sz[j] = z; ss[j] = x*x + y*y + z*z;
    }
    __syncthreads();
    int w = threadIdx.x >> 5, lane = threadIdx.x & 31;
    int n = blockIdx.x * 4 + w;
    const float* q = pf + ((size_t)b * NN + n) * 3;
    float qx = q[0], qy = q[1], qz = q[2];
    float qn = qx*qx + qy*qy + qz*qz;
    float* d = sd[w];
    for (int j = lane; j < MM; j += 32)
        d[j] = qn + ss[j] - 2.f * (qx*sx[j] + qy*sy[j] + qz*sz[j]);
    __syncwarp();
    int* out = idx_out + ((size_t)b * NN + n) * KNB;
    for (int t = 0; t < KNB; t++) {
        float best = 1e30f; int bi = 0;
        for (int j = lane; j < MM; j += 32) {
            float v = d[j];
            if (v < best || (v == best && j < bi)) { best = v; bi = j; }
        }
#pragma unroll
        for (int off = 16; off; off >>= 1) {
            float ov = __shfl_xor_sync(0xffffffffu, best, off);
            int   oi = __shfl_xor_sync(0xffffffffu, bi, off);
            if (ov < best || (ov == best && oi < bi)) { best = ov; bi = oi; }
        }
        if (lane == 0) out[t] = bi;
        if (lane == (bi & 31)) d[bi] = 1e30f;
        __syncwarp();
    }
}

// ---------------- geometry -> hrelu (PH, R) channel-major ---------------------
__global__ __launch_bounds__(256)
void geom_kernel(const float* __restrict__ pos,    // (B,3,N)
                 const float* __restrict__ seed,   // (B,M,3)
                 const int*   __restrict__ idxg,
                 const float* __restrict__ pw1,    // (64,4)
                 const float* __restrict__ aP, const float* __restrict__ cP,
                 float* __restrict__ hreluT)
{
    int r = blockIdx.x * 256 + threadIdx.x;
    int b = r >> 16;            // N*K = 65536
    int n = (r >> 4) & (NN - 1);
    int j = idxg[r];
    float px = pos[((size_t)b * 3 + 0) * NN + n];
    float py = pos[((size_t)b * 3 + 1) * NN + n];
    float pz = pos[((size_t)b * 3 + 2) * NN + n];
    const float* sj = seed + ((size_t)b * MM + j) * 3;
    float rx = px - sj[0], ry = py - sj[1], rz = pz - sj[2];
    float ds = sqrtf(rx*rx + ry*ry + rz*rz);
#pragma unroll
    for (int p = 0; p < PHD; p++) {
        float raw = __ldg(&pw1[p*4]) * ds + __ldg(&pw1[p*4+1]) * rx
                  + __ldg(&pw1[p*4+2]) * ry + __ldg(&pw1[p*4+3]) * rz;
        float h = fmaxf(raw * __ldg(&aP[p]) + __ldg(&cP[p]), 0.f);
        hreluT[(size_t)p * RR + r] = h;
    }
}

// ---------------- elementwise: hid = relu(aA*(zg + W1q - W1k) + cA) -----------
__global__ __launch_bounds__(256)
void hidfix_kernel(float* __restrict__ hid,
                   const float* __restrict__ W1qt,  // (B,N,AH)
                   const float* __restrict__ W1kt,  // (B,M,AH)
                   const int*   __restrict__ idxg,
                   const float* __restrict__ aA, const float* __restrict__ cA)
{
    size_t e4 = (size_t)blockIdx.x * 256 + threadIdx.x;   // R*AH/4 threads
    size_t e = e4 * 4;
    int r = (int)(e >> 9);
    int o = (int)(e & (AHD - 1));
    int b = r >> 16;
    int n = (r >> 4) & (NN - 1);
    int j = idxg[r];
    float4 z  = *(float4*)(hid + e);
    float4 qv = *(const float4*)(W1qt + ((size_t)b * NN + n) * AHD + o);
    float4 kv = *(const float4*)(W1kt + ((size_t)b * MM + j) * AHD + o);
    float4 av = *(const float4*)(aA + o);
    float4 cv = *(const float4*)(cA + o);
    z.x = fmaxf((z.x + qv.x - kv.x) * av.x + cv.x, 0.f);
    z.y = fmaxf((z.y + qv.y - kv.y) * av.y + cv.y, 0.f);
    z.z = fmaxf((z.z + qv.z - kv.z) * av.z + cv.z, 0.f);
    z.w = fmaxf((z.w + qv.w - kv.w) * av.w + cv.w, 0.f);
    *(float4*)(hid + e) = z;
}

// ---------------- softmax over K + gather val + aggregate ---------------------
__global__ __launch_bounds__(256)
void agg_kernel(const float* __restrict__ logits,  // (R,D)
                const float* __restrict__ pe,      // (R,D)
                const float* __restrict__ valft,   // (B,M,D)
                const int*   __restrict__ idxg,
                float* __restrict__ agg)           // (B*N, D)
{
    __shared__ int sj[KNB];
    int c = threadIdx.x;
    for (int pp = 0; pp < 16; pp++) {
        int pt = blockIdx.x * 16 + pp;
        int b = pt >> 12;
        size_t r0 = (size_t)pt * KNB;
        if (threadIdx.x < KNB) sj[threadIdx.x] = idxg[r0 + threadIdx.x];
        __syncthreads();
        float l[KNB];
        float m = -1e30f;
#pragma unroll
        for (int k = 0; k < KNB; k++) {
            l[k] = logits[(r0 + k) * DD + c];
            m = fmaxf(m, l[k]);
        }
        float S = 0.f, acc = 0.f;
#pragma unroll
        for (int k = 0; k < KNB; k++) {
            float ex = __expf(l[k] - m);
            S += ex;
            float v = valft[((size_t)b * MM + sj[k]) * DD + c];
            float p = pe[(r0 + k) * DD + c];
            acc += ex * (v + p);
        }
        agg[(size_t)pt * DD + c] = acc / S;
        __syncthreads();
    }
}

// ---------------- launch ------------------------------------------------------
extern "C" void kernel_launch(void* const* d_in, const int* in_sizes, int n_in,
                              void* d_out, int out_size)
{
    const float* pos      = (const float*)d_in[0];
    const float* pf       = (const float*)d_in[1];
    const float* fea      = (const float*)d_in[2];
    const float* seed     = (const float*)d_in[3];
    const float* seed_fea = (const float*)d_in[4];
    const float* w_start  = (const float*)d_in[5];
    const float* b_start  = (const float*)d_in[6];
    const float* w_key    = (const float*)d_in[7];
    const float* b_key    = (const float*)d_in[8];
    const float* w_value  = (const float*)d_in[9];
    const float* b_value  = (const float*)d_in[10];
    const float* w_query  = (const float*)d_in[11];
    const float* b_query  = (const float*)d_in[12];
    const float* pos_w1   = (const float*)d_in[13];
    const float* pos_b1   = (const float*)d_in[14];
    const float* pos_g1   = (const float*)d_in[15];
    const float* pos_beta1= (const float*)d_in[16];
    const float* pos_mu1  = (const float*)d_in[17];
    const float* pos_var1 = (const float*)d_in[18];
    const float* pos_w2   = (const float*)d_in[19];
    const float* pos_b2   = (const float*)d_in[20];
    const float* attn_w1  = (const float*)d_in[21];
    const float* attn_b1  = (const float*)d_in[22];
    const float* attn_g1  = (const float*)d_in[23];
    const float* attn_beta1=(const float*)d_in[24];
    const float* attn_mu1 = (const float*)d_in[25];
    const float* attn_var1= (const float*)d_in[26];
    const float* attn_w2  = (const float*)d_in[27];
    // d_in[28] = attn_b2: cancels in softmax over K
    const float* w_end    = (const float*)d_in[29];
    const float* b_end    = (const float*)d_in[30];

    float *value, *keyf, *valft, *query, *W1qt, *W1kt, *hreluT, *hid, *logits, *pe, *agg;
    float *pre1, *aA, *cA, *aP, *cP;
    int* idx;
    cudaGetSymbolAddress((void**)&value,  g_value);
    cudaGetSymbolAddress((void**)&keyf,   g_keyf);
    cudaGetSymbolAddress((void**)&valft,  g_valft);
    cudaGetSymbolAddress((void**)&query,  g_query);
    cudaGetSymbolAddress((void**)&W1qt,   g_W1qt);
    cudaGetSymbolAddress((void**)&W1kt,   g_W1kt);
    cudaGetSymbolAddress((void**)&idx,    g_idx);
    cudaGetSymbolAddress((void**)&hreluT, g_hreluT);
    cudaGetSymbolAddress((void**)&hid,    g_hid);
    cudaGetSymbolAddress((void**)&logits, g_logits);
    cudaGetSymbolAddress((void**)&pe,     g_pe);
    cudaGetSymbolAddress((void**)&agg,    g_agg);
    cudaGetSymbolAddress((void**)&pre1,   g_pre1);
    cudaGetSymbolAddress((void**)&aA,     g_aA);
    cudaGetSymbolAddress((void**)&cA,     g_cA);
    cudaGetSymbolAddress((void**)&aP,     g_aP);
    cudaGetSymbolAddress((void**)&cP,     g_cP);

    precomp_kernel<<<AHD + 1, PHD>>>(attn_w1, pos_w2, pos_b2,
                                     attn_g1, attn_beta1, attn_mu1, attn_var1, attn_b1,
                                     pos_g1, pos_beta1, pos_mu1, pos_var1, pos_b1,
                                     pre1, aA, cA, aP, cP);

    // front GEMMs
    gemm_k<false,false><<<dim3(MM/128, DD/128, BB), 256>>>(
        w_start, b_start, seed_fea, nullptr, value, DD, CC, MM,
        (size_t)CC*MM, (size_t)DD*MM);
    gemm_k<false,false><<<dim3(MM/128, DD/128, BB), 256>>>(
        w_key, b_key, value, nullptr, keyf, DD, DD, MM,
        (size_t)DD*MM, (size_t)DD*MM);
    gemm_k<false,true><<<dim3(MM/128, DD/128, BB), 256>>>(
        w_value, b_value, value, nullptr, valft, DD, DD, MM,
        (size_t)DD*MM, (size_t)MM*DD);
    gemm_k<false,false><<<dim3(NN/128, DD/128, BB), 256>>>(
        w_query, b_query, fea, nullptr, query, DD, CC, NN,
        (size_t)CC*NN, (size_t)DD*NN);
    gemm_k<false,true><<<dim3(NN/128, AHD/128, BB), 256>>>(
        attn_w1, nullptr, query, nullptr, W1qt, AHD, DD, NN,
        (size_t)DD*NN, (size_t)NN*AHD);
    gemm_k<false,true><<<dim3(MM/128, AHD/128, BB), 256>>>(
        attn_w1, nullptr, keyf, nullptr, W1kt, AHD, DD, MM,
        (size_t)DD*MM, (size_t)MM*AHD);

    // knn + geometry
    knn_kernel<<<dim3(NN/4, BB), 128>>>(pf, seed, idx);
    geom_kernel<<<RR/256, 256>>>(pos, seed, idx, pos_w1, aP, cP, hreluT);

    // zg = pre1 @ hrelu  -> hid (R,AH)
    gemm_k<false,true><<<dim3(RR/128, AHD/128, 1), 256>>>(
        pre1, nullptr, hreluT, nullptr, hid, AHD, PHD, RR, 0, 0);
    // hid = relu(aA*(zg + W1q - W1k) + cA), in place
    hidfix_kernel<<<(unsigned)((size_t)RR*AHD/4/256), 256>>>(hid, W1qt, W1kt, idx, aA, cA);
    // logits = attn_w2 @ hid
    gemm_k<true,true><<<dim3(RR/128, DD/128, 1), 256>>>(
        attn_w2, nullptr, hid, nullptr, logits, DD, AHD, RR, 0, 0);
    // pe = pos_w2 @ hrelu + pos_b2
    gemm_k<false,true><<<dim3(RR/128, DD/128, 1), 256>>>(
        pos_w2, pos_b2, hreluT, nullptr, pe, DD, PHD, RR, 0, 0);
    // softmax over K + gather + aggregate
    agg_kernel<<<BB*NN/16, 256>>>(logits, pe, valft, idx, agg);
    // out = w_end @ agg + b_end + fea
    gemm_k<true,false><<<dim3(NN/128, CC/128, BB), 256>>>(
        w_end, b_end, agg, fea, (float*)d_out, CC, DD, NN,
        (size_t)NN*DD, (size_t)CC*NN);
}

// round 2
// speedup vs baseline: 1.2878x; 1.2878x over previous
#include <cuda_runtime.h>
#include <cstdint>
#include <cstddef>

#define BB 4
#define NN 4096
#define MM 1024
#define CC 128
#define DD 256
#define PHD 64
#define AHD 512
#define KNB 16
#define RR (BB*NN*KNB)   // 262144 rows (b,n,k)

// ---------------- static scratch --------------------------------------------
__device__ float g_valueT[BB*MM*DD];     // (B*M, D) row-major
__device__ float g_keyfT [BB*MM*DD];     // (B*M, D)
__device__ float g_valftT[BB*MM*DD];     // (B*M, D)
__device__ float g_queryT[BB*NN*DD];     // (B*N, D)
__device__ float g_W1qt  [BB*NN*AHD];    // (B*N, AH)
__device__ float g_W1kt  [BB*MM*AHD];    // (B*M, AH)
__device__ int   g_idx   [RR];
__device__ float g_hrelu [16777216];     // (R, 64) row-major
__device__ float g_hid   [134217728];    // (R, 512) row-major
__device__ float g_logits[67108864];     // (R, 256)
__device__ float g_pe    [67108864];     // (R, 256)
__device__ float g_agg   [BB*NN*DD];     // (B*N, D)
__device__ float g_pre1  [AHD*PHD];      // attn_w1 @ pos_w2  (512,64)
__device__ float g_aA[AHD], g_cA[AHD], g_aP[PHD], g_cP[PHD];

// ---------------- precompute ------------------------------------------------
__global__ void precomp_kernel(const float* __restrict__ w1,
                               const float* __restrict__ pw2,
                               const float* __restrict__ pb2,
                               const float* __restrict__ ag, const float* __restrict__ abeta,
                               const float* __restrict__ amu, const float* __restrict__ avar,
                               const float* __restrict__ ab1,
                               const float* __restrict__ pg, const float* __restrict__ pbeta,
                               const float* __restrict__ pmu, const float* __restrict__ pvar,
                               const float* __restrict__ pb1,
                               float* __restrict__ pre1, float* __restrict__ aA,
                               float* __restrict__ cA, float* __restrict__ aP,
                               float* __restrict__ cP)
{
    int o = blockIdx.x;
    if (o < AHD) {
        int p = threadIdx.x;  // 64
        float s = 0.f;
        for (int c = 0; c < DD; c++) s += w1[o*DD + c] * pw2[c*PHD + p];
        pre1[o*PHD + p] = s;
        if (p == 0) {
            float vb = 0.f;
            for (int c = 0; c < DD; c++) vb += w1[o*DD + c] * pb2[c];
            float inv = ag[o] / sqrtf(avar[o] + 1e-5f);
            aA[o] = inv;
            cA[o] = (ab1[o] - amu[o]) * inv + abeta[o] + vb * inv;
        }
    } else {
        int p = threadIdx.x;
        float inv = pg[p] / sqrtf(pvar[p] + 1e-5f);
        aP[p] = inv;
        cP[p] = (pb1[p] - pmu[p]) * inv + pbeta[p];
    }
}

// ---------------- SIMT fp32 GEMM (small front/end GEMMs) --------------------
constexpr int TBO = 128, TBX = 128, TBK = 16;

template<bool A_RM, bool OUT_XO>
__global__ __launch_bounds__(256)
void gemm_k(const float* __restrict__ W, const float* __restrict__ bias,
            const float* __restrict__ A, const float* __restrict__ resid,
            float* __restrict__ C, int O, int K, int X, size_t sA, size_t sC)
{
    __shared__ float As[TBK][TBX];
    __shared__ float Ws[TBK][TBO];
    const int bx = blockIdx.x * TBX;
    const int bo = blockIdx.y * TBO;
    const int b  = blockIdx.z;
    const float* Ab = A + (size_t)b * sA;
    float* Cb = C + (size_t)b * sC;
    const int tid = threadIdx.x;
    const int tco = (tid & 15) * 4;
    const int tcx = (tid >> 4) * 4;

    float acc[8][8];
#pragma unroll
    for (int i = 0; i < 8; i++)
#pragma unroll
        for (int j = 0; j < 8; j++) acc[i][j] = 0.f;

    for (int k0 = 0; k0 < K; k0 += TBK) {
        if (A_RM) {
            int row = tid >> 1, c0 = (tid & 1) * 8;
            const float* p = Ab + (size_t)(bx + row) * K + k0 + c0;
            float4 v0 = *(const float4*)p;
            float4 v1 = *(const float4*)(p + 4);
            As[c0+0][row] = v0.x; As[c0+1][row] = v0.y;
            As[c0+2][row] = v0.z; As[c0+3][row] = v0.w;
            As[c0+4][row] = v1.x; As[c0+5][row] = v1.y;
            As[c0+6][row] = v1.z; As[c0+7][row] = v1.w;
        } else {
            int kk = tid >> 4, x8 = (tid & 15) * 8;
            const float* p = Ab + (size_t)(k0 + kk) * X + bx + x8;
            float4 v0 = *(const float4*)p;
            float4 v1 = *(const float4*)(p + 4);
            *(float4*)&As[kk][x8]     = v0;
            *(float4*)&As[kk][x8 + 4] = v1;
        }
        {
            int row = tid >> 1, c0 = (tid & 1) * 8;
            const float* p = W + (size_t)(bo + row) * K + k0 + c0;
            float4 v0 = *(const float4*)p;
            float4 v1 = *(const float4*)(p + 4);
            Ws[c0+0][row] = v0.x; Ws[c0+1][row] = v0.y;
            Ws[c0+2][row] = v0.z; Ws[c0+3][row] = v0.w;
            Ws[c0+4][row] = v1.x; Ws[c0+5][row] = v1.y;
            Ws[c0+6][row] = v1.z; Ws[c0+7][row] = v1.w;
        }
        __syncthreads();
#pragma unroll
        for (int kk = 0; kk < TBK; kk++) {
            float4 a0 = *(const float4*)&As[kk][tcx];
            float4 a1 = *(const float4*)&As[kk][tcx + 64];
            float4 w0 = *(const float4*)&Ws[kk][tco];
            float4 w1 = *(const float4*)&Ws[kk][tco + 64];
            float a[8] = {a0.x, a0.y, a0.z, a0.w, a1.x, a1.y, a1.z, a1.w};
            float w[8] = {w0.x, w0.y, w0.z, w0.w, w1.x, w1.y, w1.z, w1.w};
#pragma unroll
            for (int i = 0; i < 8; i++)
#pragma unroll
                for (int j = 0; j < 8; j++)
                    acc[i][j] = fmaf(a[i], w[j], acc[i][j]);
        }
        __syncthreads();
    }
#pragma unroll
    for (int i = 0; i < 8; i++) {
        int xx = bx + (i < 4 ? tcx + i : 64 + tcx + (i - 4));
#pragma unroll
        for (int jh = 0; jh < 2; jh++) {
            int oo = bo + tco + jh * 64;
            float vr[4];
#pragma unroll
            for (int j = 0; j < 4; j++) vr[j] = acc[i][jh * 4 + j];
            if (bias) {
#pragma unroll
                for (int j = 0; j < 4; j++) vr[j] += bias[oo + j];
            }
            if (OUT_XO) {
                size_t ix = (size_t)xx * O + oo;
                if (resid) {
                    float4 rv = *(const float4*)(resid + (size_t)b * sC + ix);
                    vr[0] += rv.x; vr[1] += rv.y; vr[2] += rv.z; vr[3] += rv.w;
                }
                float4 ov = {vr[0], vr[1], vr[2], vr[3]};
                *(float4*)(Cb + ix) = ov;
            } else {
#pragma unroll
                for (int j = 0; j < 4; j++) {
                    size_t ix = (size_t)(oo + j) * X + xx;
                    float v = vr[j];
                    if (resid) v += resid[(size_t)b * sC + ix];
                    Cb[ix] = v;
                }
            }
        }
    }
}

// ---------------- tf32 tensor-core GEMM: C(rows,O) = A(rows,K) @ W(O,K)^T ----
// BM=128, BN=128, BK=32, 256 threads = 8 warps (4M x 2N), warp tile 32x64.
// EPI 0: +bias (optional).  EPI 1: hid = relu((acc + W1q[n] - W1k[j])*aA + cA)
__device__ __forceinline__ uint32_t f2tf(float f) {
    uint32_t u;
    asm("cvt.rna.tf32.f32 %0, %1;" : "=r"(u) : "f"(f));
    return u;
}

template<int EPI>
__global__ __launch_bounds__(256)
void mma_gemm(const float* __restrict__ W, const float* __restrict__ bias,
              const float* __restrict__ A, float* __restrict__ C,
              int O, int K,
              const float* __restrict__ W1q, const float* __restrict__ W1k,
              const int* __restrict__ idxg,
              const float* __restrict__ aA, const float* __restrict__ cA)
{
    __shared__ uint32_t As[128][36];   // pad 36 -> bank = (4m+k)%32, conflict-free
    __shared__ uint32_t Bs[128][36];
    const int row0 = blockIdx.y * 128;
    const int o0   = blockIdx.x * 128;
    const int tid  = threadIdx.x;
    const int lane = tid & 31;
    const int wid  = tid >> 5;
    const int wm = wid & 3;     // M group (32 rows)
    const int wn = wid >> 2;    // N group (64 cols)
    const int lq = lane >> 2;   // 0..7
    const int lr = lane & 3;    // 0..3

    float acc[2][8][4];
#pragma unroll
    for (int mt = 0; mt < 2; mt++)
#pragma unroll
        for (int nt = 0; nt < 8; nt++)
#pragma unroll
            for (int q = 0; q < 4; q++) acc[mt][nt][q] = 0.f;

    for (int k0 = 0; k0 < K; k0 += 32) {
#pragma unroll
        for (int i = 0; i < 4; i++) {
            int lin = tid + i * 256;           // 0..1023
            int m = lin >> 3, kq = (lin & 7) << 2;
            float4 va = *(const float4*)(A + (size_t)(row0 + m) * K + k0 + kq);
            uint4 ua = { f2tf(va.x), f2tf(va.y), f2tf(va.z), f2tf(va.w) };
            *(uint4*)&As[m][kq] = ua;
            float4 vb = *(const float4*)(W + (size_t)(o0 + m) * K + k0 + kq);
            uint4 ub = { f2tf(vb.x), f2tf(vb.y), f2tf(vb.z), f2tf(vb.w) };
            *(uint4*)&Bs[m][kq] = ub;
        }
        __syncthreads();
#pragma unroll
        for (int ks = 0; ks < 4; ks++) {
            int kk = ks * 8 + lr;
            uint32_t bf[8][2];
#pragma unroll
            for (int nt = 0; nt < 8; nt++) {
                int cb = wn * 64 + nt * 8 + lq;
                bf[nt][0] = Bs[cb][kk];
                bf[nt][1] = Bs[cb][kk + 4];
            }
#pragma unroll
            for (int mt = 0; mt < 2; mt++) {
                int rb = wm * 32 + mt * 16 + lq;
                uint32_t a0 = As[rb][kk];
                uint32_t a1 = As[rb + 8][kk];
                uint32_t a2 = As[rb][kk + 4];
                uint32_t a3 = As[rb + 8][kk + 4];
#pragma unroll
                for (int nt = 0; nt < 8; nt++) {
                    asm volatile(
                        "mma.sync.aligned.m16n8k8.row.col.f32.tf32.tf32.f32 "
                        "{%0,%1,%2,%3},{%4,%5,%6,%7},{%8,%9},{%0,%1,%2,%3};"
                        : "+f"(acc[mt][nt][0]), "+f"(acc[mt][nt][1]),
                          "+f"(acc[mt][nt][2]), "+f"(acc[mt][nt][3])
                        : "r"(a0), "r"(a1), "r"(a2), "r"(a3),
                          "r"(bf[nt][0]), "r"(bf[nt][1]));
                }
            }
        }
        __syncthreads();
    }
    // epilogue
#pragma unroll
    for (int mt = 0; mt < 2; mt++) {
#pragma unroll
        for (int h = 0; h < 2; h++) {
            int r = row0 + wm * 32 + mt * 16 + h * 8 + lq;
            const float* qp = nullptr;
            const float* kp = nullptr;
            if (EPI == 1) {
                int b = r >> 16;
                int j = idxg[r];
                qp = W1q + (size_t)(r >> 4) * AHD;
                kp = W1k + (size_t)(b * MM + j) * AHD;
            }
            float* crow = C + (size_t)r * O + o0 + wn * 64;
#pragma unroll
            for (int nt = 0; nt < 8; nt++) {
                int oc = nt * 8 + lr * 2;
                int o  = o0 + wn * 64 + oc;
                float v0 = acc[mt][nt][h * 2 + 0];
                float v1 = acc[mt][nt][h * 2 + 1];
                if (EPI == 0) {
                    if (bias) { v0 += bias[o]; v1 += bias[o + 1]; }
                } else {
                    float2 qv = *(const float2*)(qp + o);
                    float2 kv = *(const float2*)(kp + o);
                    float2 av = *(const float2*)(aA + o);
                    float2 cv = *(const float2*)(cA + o);
                    v0 = fmaxf((v0 + qv.x - kv.x) * av.x + cv.x, 0.f);
                    v1 = fmaxf((v1 + qv.y - kv.y) * av.y + cv.y, 0.f);
                }
                *(float2*)&crow[oc] = make_float2(v0, v1);
            }
        }
    }
}

// ---------------- KNN -------------------------------------------------------
__global__ __launch_bounds__(128)
void knn_kernel(const float* __restrict__ pf,
                const float* __restrict__ seed,
                int* __restrict__ idx_out)
{
    __shared__ float sx[MM], sy[MM], sz[MM], ss[MM];
    __shared__ float sd[4][MM];
    int b = blockIdx.y;
    const float* sb = seed + (size_t)b * MM * 3;
    for (int j = threadIdx.x; j < MM; j += 128) {
        float x = sb[j*3], y = sb[j*3+1], z = sb[j*3+2];
        sx[j] = x; sy[j] = y; sz[j] = z; ss[j] = x*x + y*y + z*z;
    }
    __syncthreads();
    int w = threadIdx.x >> 5, lane = threadIdx.x & 31;
    int n = blockIdx.x * 4 + w;
    const float* q = pf + ((size_t)b * NN + n) * 3;
    float qx = q[0], qy = q[1], qz = q[2];
    float qn = qx*qx + qy*qy + qz*qz;
    float* d = sd[w];
    for (int j = lane; j < MM; j += 32)
        d[j] = qn + ss[j] - 2.f * (qx*sx[j] + qy*sy[j] + qz*sz[j]);
    __syncwarp();
    int* out = idx_out + ((size_t)b * NN + n) * KNB;
    for (int t = 0; t < KNB; t++) {
        float best = 1e30f; int bi = 0;
        for (int j = lane; j < MM; j += 32) {
            float v = d[j];
            if (v < best || (v == best && j < bi)) { best = v; bi = j; }
        }
#pragma unroll
        for (int off = 16; off; off >>= 1) {
            float ov = __shfl_xor_sync(0xffffffffu, best, off);
            int   oi = __shfl_xor_sync(0xffffffffu, bi, off);
            if (ov < best || (ov == best && oi < bi)) { best = ov; bi = oi; }
        }
        if (lane == 0) out[t] = bi;
        if (lane == (bi & 31)) d[bi] = 1e30f;
        __syncwarp();
    }
}

// ---------------- geometry -> hrelu (R,64) row-major -------------------------
__global__ __launch_bounds__(256)
void geom_kernel(const float* __restrict__ pos,
                 const float* __restrict__ seed,
                 const int*   __restrict__ idxg,
                 const float* __restrict__ pw1,
                 const float* __restrict__ aP, const float* __restrict__ cP,
                 float* __restrict__ hrelu)
{
    int r = blockIdx.x * 256 + threadIdx.x;
    int b = r >> 16;
    int n = (r >> 4) & (NN - 1);
    int j = idxg[r];
    float px = pos[((size_t)b * 3 + 0) * NN + n];
    float py = pos[((size_t)b * 3 + 1) * NN + n];
    float pz = pos[((size_t)b * 3 + 2) * NN + n];
    const float* sj = seed + ((size_t)b * MM + j) * 3;
    float rx = px - sj[0], ry = py - sj[1], rz = pz - sj[2];
    float ds = sqrtf(rx*rx + ry*ry + rz*rz);
    float* out = hrelu + (size_t)r * PHD;
#pragma unroll
    for (int p0 = 0; p0 < PHD; p0 += 4) {
        float4 v;
        float t[4];
#pragma unroll
        for (int u = 0; u < 4; u++) {
            int p = p0 + u;
            float raw = __ldg(&pw1[p*4]) * ds + __ldg(&pw1[p*4+1]) * rx
                      + __ldg(&pw1[p*4+2]) * ry + __ldg(&pw1[p*4+3]) * rz;
            t[u] = fmaxf(raw * __ldg(&aP[p]) + __ldg(&cP[p]), 0.f);
        }
        v.x = t[0]; v.y = t[1]; v.z = t[2]; v.w = t[3];
        *(float4*)(out + p0) = v;
    }
}

// ---------------- softmax over K + gather val + aggregate --------------------
__global__ __launch_bounds__(256)
void agg_kernel(const float* __restrict__ logits,
                const float* __restrict__ pe,
                const float* __restrict__ valft,
                const int*   __restrict__ idxg,
                float* __restrict__ agg)
{
    __shared__ int sj[KNB];
    int c = threadIdx.x;
    for (int pp = 0; pp < 16; pp++) {
        int pt = blockIdx.x * 16 + pp;
        int b = pt >> 12;
        size_t r0 = (size_t)pt * KNB;
        if (threadIdx.x < KNB) sj[threadIdx.x] = idxg[r0 + threadIdx.x];
        __syncthreads();
        float l[KNB];
        float m = -1e30f;
#pragma unroll
        for (int k = 0; k < KNB; k++) {
            l[k] = logits[(r0 + k) * DD + c];
            m = fmaxf(m, l[k]);
        }
        float S = 0.f, acc = 0.f;
#pragma unroll
        for (int k = 0; k < KNB; k++) {
            float ex = __expf(l[k] - m);
            S += ex;
            float v = valft[((size_t)b * MM + sj[k]) * DD + c];
            float p = pe[(r0 + k) * DD + c];
            acc += ex * (v + p);
        }
        agg[(size_t)pt * DD + c] = acc / S;
        __syncthreads();
    }
}

// ---------------- launch -----------------------------------------------------
extern "C" void kernel_launch(void* const* d_in, const int* in_sizes, int n_in,
                              void* d_out, int out_size)
{
    const float* pos      = (const float*)d_in[0];
    const float* pf       = (const float*)d_in[1];
    const float* fea      = (const float*)d_in[2];
    const float* seed     = (const float*)d_in[3];
    const float* seed_fea = (const float*)d_in[4];
    const float* w_start  = (const float*)d_in[5];
    const float* b_start  = (const float*)d_in[6];
    const float* w_key    = (const float*)d_in[7];
    const float* b_key    = (const float*)d_in[8];
    const float* w_value  = (const float*)d_in[9];
    const float* b_value  = (const float*)d_in[10];
    const float* w_query  = (const float*)d_in[11];
    const float* b_query  = (const float*)d_in[12];
    const float* pos_w1   = (const float*)d_in[13];
    const float* pos_b1   = (const float*)d_in[14];
    const float* pos_g1   = (const float*)d_in[15];
    const float* pos_beta1= (const float*)d_in[16];
    const float* pos_mu1  = (const float*)d_in[17];
    const float* pos_var1 = (const float*)d_in[18];
    const float* pos_w2   = (const float*)d_in[19];
    const float* pos_b2   = (const float*)d_in[20];
    const float* attn_w1  = (const float*)d_in[21];
    const float* attn_b1  = (const float*)d_in[22];
    const float* attn_g1  = (const float*)d_in[23];
    const float* attn_beta1=(const float*)d_in[24];
    const float* attn_mu1 = (const float*)d_in[25];
    const float* attn_var1= (const float*)d_in[26];
    const float* attn_w2  = (const float*)d_in[27];
    // d_in[28] = attn_b2: cancels in softmax over K
    const float* w_end    = (const float*)d_in[29];
    const float* b_end    = (const float*)d_in[30];

    float *valueT, *keyfT, *valftT, *queryT, *W1qt, *W1kt, *hrelu, *hid, *logits, *pe, *agg;
    float *pre1, *aA, *cA, *aP, *cP;
    int* idx;
    cudaGetSymbolAddress((void**)&valueT, g_valueT);
    cudaGetSymbolAddress((void**)&keyfT,  g_keyfT);
    cudaGetSymbolAddress((void**)&valftT, g_valftT);
    cudaGetSymbolAddress((void**)&queryT, g_queryT);
    cudaGetSymbolAddress((void**)&W1qt,   g_W1qt);
    cudaGetSymbolAddress((void**)&W1kt,   g_W1kt);
    cudaGetSymbolAddress((void**)&idx,    g_idx);
    cudaGetSymbolAddress((void**)&hrelu,  g_hrelu);
    cudaGetSymbolAddress((void**)&hid,    g_hid);
    cudaGetSymbolAddress((void**)&logits, g_logits);
    cudaGetSymbolAddress((void**)&pe,     g_pe);
    cudaGetSymbolAddress((void**)&agg,    g_agg);
    cudaGetSymbolAddress((void**)&pre1,   g_pre1);
    cudaGetSymbolAddress((void**)&aA,     g_aA);
    cudaGetSymbolAddress((void**)&cA,     g_cA);
    cudaGetSymbolAddress((void**)&aP,     g_aP);
    cudaGetSymbolAddress((void**)&cP,     g_cP);

    precomp_kernel<<<AHD + 1, PHD>>>(attn_w1, pos_w2, pos_b2,
                                     attn_g1, attn_beta1, attn_mu1, attn_var1, attn_b1,
                                     pos_g1, pos_beta1, pos_mu1, pos_var1, pos_b1,
                                     pre1, aA, cA, aP, cP);

    // front GEMMs (SIMT, row-major outputs)
    gemm_k<false,true><<<dim3(MM/128, DD/128, BB), 256>>>(
        w_start, b_start, seed_fea, nullptr, valueT, DD, CC, MM,
        (size_t)CC*MM, (size_t)MM*DD);
    gemm_k<true,true><<<dim3(MM/128, DD/128, BB), 256>>>(
        w_key, b_key, valueT, nullptr, keyfT, DD, DD, MM,
        (size_t)MM*DD, (size_t)MM*DD);
    gemm_k<true,true><<<dim3(MM/128, DD/128, BB), 256>>>(
        w_value, b_value, valueT, nullptr, valftT, DD, DD, MM,
        (size_t)MM*DD, (size_t)MM*DD);
    gemm_k<false,true><<<dim3(NN/128, DD/128, BB), 256>>>(
        w_query, b_query, fea, nullptr, queryT, DD, CC, NN,
        (size_t)CC*NN, (size_t)NN*DD);

    // W1q / W1k via tensor cores
    mma_gemm<0><<<dim3(AHD/128, BB*NN/128), 256>>>(
        attn_w1, nullptr, queryT, W1qt, AHD, DD,
        nullptr, nullptr, nullptr, nullptr, nullptr);
    mma_gemm<0><<<dim3(AHD/128, BB*MM/128), 256>>>(
        attn_w1, nullptr, keyfT, W1kt, AHD, DD,
        nullptr, nullptr, nullptr, nullptr, nullptr);

    // knn + geometry
    knn_kernel<<<dim3(NN/4, BB), 128>>>(pf, seed, idx);
    geom_kernel<<<RR/256, 256>>>(pos, seed, idx, pos_w1, aP, cP, hrelu);

    // hid = relu(aA*(pre1@hrelu + W1q - W1k) + cA)   (fused epilogue)
    mma_gemm<1><<<dim3(AHD/128, RR/128), 256>>>(
        pre1, nullptr, hrelu, hid, AHD, PHD,
        W1qt, W1kt, idx, aA, cA);
    // logits = attn_w2 @ hid
    mma_gemm<0><<<dim3(DD/128, RR/128), 256>>>(
        attn_w2, nullptr, hid, logits, DD, AHD,
        nullptr, nullptr, nullptr, nullptr, nullptr);
    // pe = pos_w2 @ hrelu + pos_b2
    mma_gemm<0><<<dim3(DD/128, RR/128), 256>>>(
        pos_w2, pos_b2, hrelu, pe, DD, PHD,
        nullptr, nullptr, nullptr, nullptr, nullptr);

    // softmax + gather + aggregate
    agg_kernel<<<BB*NN/16, 256>>>(logits, pe, valftT, idx, agg);
    // out = w_end @ agg + b_end + fea
    gemm_k<true,false><<<dim3(NN/128, CC/128, BB), 256>>>(
        w_end, b_end, agg, fea, (float*)d_out, CC, DD, NN,
        (size_t)NN*DD, (size_t)CC*NN);
}

// round 7
// speedup vs baseline: 2.4041x; 1.8668x over previous
#include <cuda_runtime.h>
#include <cuda_fp16.h>
#include <cstdint>
#include <cstddef>

#define BB 4
#define NN 4096
#define MM 1024
#define CC 128
#define DD 256
#define PHD 64
#define AHD 512
#define KNB 16
#define RR (BB*NN*KNB)   // 262144 rows (b,n,k)

// ---------------- static scratch --------------------------------------------
__device__ float  g_valueT[BB*MM*DD];     // (B*M, D)
__device__ float  g_keyfT [BB*MM*DD];
__device__ float  g_valftT[BB*MM*DD];
__device__ float  g_queryT[BB*NN*DD];     // (B*N, D)
__device__ float  g_W1qt  [BB*NN*AHD];    // (B*N, AH) fp32
__device__ float  g_W1kt  [BB*MM*AHD];    // (B*M, AH) fp32
__device__ int    g_idx   [RR];
__device__ __half g_hrelu [16777216];     // (R, 64) fp16
__device__ __half g_hid   [134217728];    // (R, 512) fp16
__device__ float  g_logits[67108864];     // (R, 256) fp32
__device__ float  g_pe    [67108864];     // (R, 256) fp32
__device__ float  g_agg   [BB*NN*DD];
__device__ float  g_pre1  [AHD*PHD];
__device__ __half g_pre1h [AHD*PHD];
__device__ __half g_w1h   [AHD*DD];       // attn_w1 fp16
__device__ __half g_w2h   [DD*AHD];       // attn_w2 fp16
__device__ __half g_pw2h  [DD*PHD];       // pos_w2 fp16
__device__ float  g_aA[AHD], g_cA[AHD], g_aP[PHD], g_cP[PHD];

// ---------------- helpers ----------------------------------------------------
__device__ __forceinline__ void mma16816(float* d, const uint32_t* a,
                                         uint32_t b0, uint32_t b1) {
    asm volatile(
        "mma.sync.aligned.m16n8k16.row.col.f32.f16.f16.f32 "
        "{%0,%1,%2,%3},{%4,%5,%6,%7},{%8,%9},{%0,%1,%2,%3};"
        : "+f"(d[0]), "+f"(d[1]), "+f"(d[2]), "+f"(d[3])
        : "r"(a[0]), "r"(a[1]), "r"(a[2]), "r"(a[3]), "r"(b0), "r"(b1));
}
__device__ __forceinline__ uint32_t packh2(float x, float y) {
    __half2 h = __floats2half2_rn(x, y);
    return *(uint32_t*)&h;
}

// ---------------- fp16 mma GEMM: C(rows,O) = A(rows,K) @ W(O,K)^T -------------
// BM=128, BN=128, BK=32. 256 threads = 8 warps (4M x 2N), warp tile 32x64.
// Smem: half2 words, [128][20] (16 data + 4 pad) -> conflict-free scalar LDS.
// A: fp16 (AF16) or fp32 (converted at staging). W: fp16.
// EPI 0: C = acc (+bias fp32).   EPI 1: C = relu((acc+W1q-W1k)*aA+cA)
template<int O, int K, int EPI, bool AF16, bool OUTH>
__global__ __launch_bounds__(256)
void hgemm(const __half* __restrict__ Wh, const float* __restrict__ bias,
           const void* __restrict__ Ag, void* __restrict__ Cg,
           const float* __restrict__ W1q, const float* __restrict__ W1k,
           const int* __restrict__ idxg,
           const float* __restrict__ aA, const float* __restrict__ cA)
{
    constexpr int CCH = K / 32;
    __shared__ __align__(16) __half2 As2[128][20];
    __shared__ __align__(16) __half2 Bs2[128][20];
    const int row0 = blockIdx.y * 128;
    const int o0   = blockIdx.x * 128;
    const int tid  = threadIdx.x;
    const int lane = tid & 31;
    const int wid  = tid >> 5;
    const int wm = wid & 3;       // 32-row group
    const int wn = wid >> 2;      // 64-col group
    const int lq = lane >> 2;     // 0..7
    const int lr = lane & 3;      // 0..3

    float acc[2][8][4];
#pragma unroll
    for (int mt = 0; mt < 2; mt++)
#pragma unroll
        for (int nt = 0; nt < 8; nt++)
#pragma unroll
            for (int q = 0; q < 4; q++) acc[mt][nt][q] = 0.f;

    uint4  ra[2], rbv[2];
    float4 fa[2][2];

    auto fetch = [&](int c) {
        if (AF16) {
            const __half* s = (const __half*)Ag +
                (size_t)(row0 + (tid >> 1)) * K + c * 32 + (tid & 1) * 16;
            ra[0] = *(const uint4*)s;
            ra[1] = *(const uint4*)(s + 8);
        } else {
#pragma unroll
            for (int i = 0; i < 2; i++) {
                int lin = tid + i * 256;
                int r = lin >> 2, cq = (lin & 3) * 4;
                const float* s = (const float*)Ag +
                    (size_t)(row0 + r) * K + c * 32 + cq * 2;
                fa[i][0] = *(const float4*)s;
                fa[i][1] = *(const float4*)(s + 4);
            }
        }
        const __half* w = Wh + (size_t)(o0 + (tid >> 1)) * K + c * 32 + (tid & 1) * 16;
        rbv[0] = *(const uint4*)w;
        rbv[1] = *(const uint4*)(w + 8);
    };
    auto store = [&]() {
        int r = tid >> 1, c0 = (tid & 1) * 8;
        if (AF16) {
            *(uint4*)&As2[r][c0]     = ra[0];
            *(uint4*)&As2[r][c0 + 4] = ra[1];
        } else {
#pragma unroll
            for (int i = 0; i < 2; i++) {
                int lin = tid + i * 256;
                int rr = lin >> 2, cq = (lin & 3) * 4;
                uint4 u;
                u.x = packh2(fa[i][0].x, fa[i][0].y);
                u.y = packh2(fa[i][0].z, fa[i][0].w);
                u.z = packh2(fa[i][1].x, fa[i][1].y);
                u.w = packh2(fa[i][1].z, fa[i][1].w);
                *(uint4*)&As2[rr][cq] = u;
            }
        }
        *(uint4*)&Bs2[r][c0]     = rbv[0];
        *(uint4*)&Bs2[r][c0 + 4] = rbv[1];
    };

    fetch(0);
#pragma unroll 1
    for (int c = 0; c < CCH; c++) {
        store();
        __syncthreads();
        if (c + 1 < CCH) fetch(c + 1);   // LDG overlapped with MMA below
#pragma unroll
        for (int ks = 0; ks < 2; ks++) {
            const int kb = ks * 8 + lr;
            uint32_t bf[8][2];
#pragma unroll
            for (int nt = 0; nt < 8; nt++) {
                int cb = wn * 64 + nt * 8 + lq;
                bf[nt][0] = *(const uint32_t*)&Bs2[cb][kb];
                bf[nt][1] = *(const uint32_t*)&Bs2[cb][kb + 4];
            }
#pragma unroll
            for (int mt = 0; mt < 2; mt++) {
                int rb = wm * 32 + mt * 16 + lq;
                uint32_t a[4];
                a[0] = *(const uint32_t*)&As2[rb][kb];
                a[1] = *(const uint32_t*)&As2[rb + 8][kb];
                a[2] = *(const uint32_t*)&As2[rb][kb + 4];
                a[3] = *(const uint32_t*)&As2[rb + 8][kb + 4];
#pragma unroll
                for (int nt = 0; nt < 8; nt++)
                    mma16816(acc[mt][nt], a, bf[nt][0], bf[nt][1]);
            }
        }
        __syncthreads();
    }

    // ---- epilogue ----
#pragma unroll
    for (int mt = 0; mt < 2; mt++) {
#pragma unroll
        for (int h = 0; h < 2; h++) {
            int r = row0 + wm * 32 + mt * 16 + h * 8 + lq;
            const float* qp = nullptr;
            const float* kp = nullptr;
            if (EPI == 1) {
                int bbx = r >> 16;
                int jj = idxg[r];
                qp = W1q + (size_t)(r >> 4) * AHD;
                kp = W1k + ((size_t)bbx * MM + jj) * AHD;
            }
#pragma unroll
            for (int nt = 0; nt < 8; nt++) {
                int o = o0 + wn * 64 + nt * 8 + lr * 2;
                float v0 = acc[mt][nt][h * 2 + 0];
                float v1 = acc[mt][nt][h * 2 + 1];
                if (EPI == 0) {
                    if (bias) { v0 += bias[o]; v1 += bias[o + 1]; }
                } else {
                    float2 qv = *(const float2*)(qp + o);
                    float2 kv = *(const float2*)(kp + o);
                    float2 av = *(const float2*)(aA + o);
                    float2 cv = *(const float2*)(cA + o);
                    v0 = fmaxf((v0 + qv.x - kv.x) * av.x + cv.x, 0.f);
                    v1 = fmaxf((v1 + qv.y - kv.y) * av.y + cv.y, 0.f);
                }
                if (OUTH) {
                    __half2 hv = __floats2half2_rn(v0, v1);
                    *(__half2*)((__half*)Cg + (size_t)r * O + o) = hv;
                } else {
                    *(float2*)((float*)Cg + (size_t)r * O + o) = make_float2(v0, v1);
                }
            }
        }
    }
}

// ---------------- precompute + weight conversions ----------------------------
__global__ void precomp_kernel(const float* __restrict__ w1,
                               const float* __restrict__ pw2,
                               const float* __restrict__ pb2,
                               const float* __restrict__ ag, const float* __restrict__ abeta,
                               const float* __restrict__ amu, const float* __restrict__ avar,
                               const float* __restrict__ ab1,
                               const float* __restrict__ pg, const float* __restrict__ pbeta,
                               const float* __restrict__ pmu, const float* __restrict__ pvar,
                               const float* __restrict__ pb1,
                               float* __restrict__ pre1, __half* __restrict__ pre1h,
                               float* __restrict__ aA,
                               float* __restrict__ cA, float* __restrict__ aP,
                               float* __restrict__ cP)
{
    int o = blockIdx.x;
    if (o < AHD) {
        int p = threadIdx.x;
        float s = 0.f;
        for (int c = 0; c < DD; c++) s += w1[o*DD + c] * pw2[c*PHD + p];
        pre1[o*PHD + p] = s;
        pre1h[o*PHD + p] = __float2half_rn(s);
        if (p == 0) {
            float vb = 0.f;
            for (int c = 0; c < DD; c++) vb += w1[o*DD + c] * pb2[c];
            float inv = ag[o] / sqrtf(avar[o] + 1e-5f);
            aA[o] = inv;
            cA[o] = (ab1[o] - amu[o]) * inv + abeta[o] + vb * inv;
        }
    } else {
        int p = threadIdx.x;
        float inv = pg[p] / sqrtf(pvar[p] + 1e-5f);
        aP[p] = inv;
        cP[p] = (pb1[p] - pmu[p]) * inv + pbeta[p];
    }
}

__global__ void cvt_h_kernel(const float* __restrict__ s, __half* __restrict__ d, int n)
{
    int i = blockIdx.x * 256 + threadIdx.x;
    if (i < n) d[i] = __float2half_rn(s[i]);
}

// ---------------- SIMT fp32 GEMM (small front/end GEMMs) ---------------------
constexpr int TBO = 128, TBX = 128, TBK = 16;

template<bool A_RM, bool OUT_XO>
__global__ __launch_bounds__(256)
void gemm_k(const float* __restrict__ W, const float* __restrict__ bias,
            const float* __restrict__ A, const float* __restrict__ resid,
            float* __restrict__ C, int O, int K, int X, size_t sA, size_t sC)
{
    __shared__ float As[TBK][TBX];
    __shared__ float Ws[TBK][TBO];
    const int bx = blockIdx.x * TBX;
    const int bo = blockIdx.y * TBO;
    const int b  = blockIdx.z;
    const float* Ab = A + (size_t)b * sA;
    float* Cb = C + (size_t)b * sC;
    const int tid = threadIdx.x;
    const int tco = (tid & 15) * 4;
    const int tcx = (tid >> 4) * 4;

    float acc[8][8];
#pragma unroll
    for (int i = 0; i < 8; i++)
#pragma unroll
        for (int j = 0; j < 8; j++) acc[i][j] = 0.f;

    for (int k0 = 0; k0 < K; k0 += TBK) {
        if (A_RM) {
            int row = tid >> 1, c0 = (tid & 1) * 8;
            const float* p = Ab + (size_t)(bx + row) * K + k0 + c0;
            float4 v0 = *(const float4*)p;
            float4 v1 = *(const float4*)(p + 4);
            As[c0+0][row] = v0.x; As[c0+1][row] = v0.y;
            As[c0+2][row] = v0.z; As[c0+3][row] = v0.w;
            As[c0+4][row] = v1.x; As[c0+5][row] = v1.y;
            As[c0+6][row] = v1.z; As[c0+7][row] = v1.w;
        } else {
            int kk = tid >> 4, x8 = (tid & 15) * 8;
            const float* p = Ab + (size_t)(k0 + kk) * X + bx + x8;
            float4 v0 = *(const float4*)p;
            float4 v1 = *(const float4*)(p + 4);
            *(float4*)&As[kk][x8]     = v0;
            *(float4*)&As[kk][x8 + 4] = v1;
        }
        {
            int row = tid >> 1, c0 = (tid & 1) * 8;
            const float* p = W + (size_t)(bo + row) * K + k0 + c0;
            float4 v0 = *(const float4*)p;
            float4 v1 = *(const float4*)(p + 4);
            Ws[c0+0][row] = v0.x; Ws[c0+1][row] = v0.y;
            Ws[c0+2][row] = v0.z; Ws[c0+3][row] = v0.w;
            Ws[c0+4][row] = v1.x; Ws[c0+5][row] = v1.y;
            Ws[c0+6][row] = v1.z; Ws[c0+7][row] = v1.w;
        }
        __syncthreads();
#pragma unroll
        for (int kk = 0; kk < TBK; kk++) {
            float4 a0 = *(const float4*)&As[kk][tcx];
            float4 a1 = *(const float4*)&As[kk][tcx + 64];
            float4 w0 = *(const float4*)&Ws[kk][tco];
            float4 w1 = *(const float4*)&Ws[kk][tco + 64];
            float a[8] = {a0.x, a0.y, a0.z, a0.w, a1.x, a1.y, a1.z, a1.w};
            float w[8] = {w0.x, w0.y, w0.z, w0.w, w1.x, w1.y, w1.z, w1.w};
#pragma unroll
            for (int i = 0; i < 8; i++)
#pragma unroll
                for (int j = 0; j < 8; j++)
                    acc[i][j] = fmaf(a[i], w[j], acc[i][j]);
        }
        __syncthreads();
    }
#pragma unroll
    for (int i = 0; i < 8; i++) {
        int xx = bx + (i < 4 ? tcx + i : 64 + tcx + (i - 4));
#pragma unroll
        for (int jh = 0; jh < 2; jh++) {
            int oo = bo + tco + jh * 64;
            float vr[4];
#pragma unroll
            for (int j = 0; j < 4; j++) vr[j] = acc[i][jh * 4 + j];
            if (bias) {
#pragma unroll
                for (int j = 0; j < 4; j++) vr[j] += bias[oo + j];
            }
            if (OUT_XO) {
                size_t ix = (size_t)xx * O + oo;
                if (resid) {
                    float4 rv = *(const float4*)(resid + (size_t)b * sC + ix);
                    vr[0] += rv.x; vr[1] += rv.y; vr[2] += rv.z; vr[3] += rv.w;
                }
                float4 ov = {vr[0], vr[1], vr[2], vr[3]};
                *(float4*)(Cb + ix) = ov;
            } else {
#pragma unroll
                for (int j = 0; j < 4; j++) {
                    size_t ix = (size_t)(oo + j) * X + xx;
                    float v = vr[j];
                    if (resid) v += resid[(size_t)b * sC + ix];
                    Cb[ix] = v;
                }
            }
        }
    }
}

// ---------------- KNN --------------------------------------------------------
__global__ __launch_bounds__(128)
void knn_kernel(const float* __restrict__ pf,
                const float* __restrict__ seed,
                int* __restrict__ idx_out)
{
    __shared__ float sx[MM], sy[MM], sz[MM], ss[MM];
    __shared__ float sd[4][MM];
    int b = blockIdx.y;
    const float* sb = seed + (size_t)b * MM * 3;
    for (int j = threadIdx.x; j < MM; j += 128) {
        float x = sb[j*3], y = sb[j*3+1], z = sb[j*3+2];
        sx[j] = x; sy[j] = y; sz[j] = z; ss[j] = x*x + y*y + z*z;
    }
    __syncthreads();
    int w = threadIdx.x >> 5, lane = threadIdx.x & 31;
    int n = blockIdx.x * 4 + w;
    const float* q = pf + ((size_t)b * NN + n) * 3;
    float qx = q[0], qy = q[1], qz = q[2];
    float qn = qx*qx + qy*qy + qz*qz;
    float* d = sd[w];
    for (int j = lane; j < MM; j += 32)
        d[j] = qn + ss[j] - 2.f * (qx*sx[j] + qy*sy[j] + qz*sz[j]);
    __syncwarp();
    int* out = idx_out + ((size_t)b * NN + n) * KNB;
    for (int t = 0; t < KNB; t++) {
        float best = 1e30f; int bi = 0;
        for (int j = lane; j < MM; j += 32) {
            float v = d[j];
            if (v < best || (v == best && j < bi)) { best = v; bi = j; }
        }
#pragma unroll
        for (int off = 16; off; off >>= 1) {
            float ov = __shfl_xor_sync(0xffffffffu, best, off);
            int   oi = __shfl_xor_sync(0xffffffffu, bi, off);
            if (ov < best || (ov == best && oi < bi)) { best = ov; bi = oi; }
        }
        if (lane == 0) out[t] = bi;
        if (lane == (bi & 31)) d[bi] = 1e30f;
        __syncwarp();
    }
}

// ---------------- geometry -> hrelu (R,64) fp16 ------------------------------
__global__ __launch_bounds__(256)
void geom_kernel(const float* __restrict__ pos,
                 const float* __restrict__ seed,
                 const int*   __restrict__ idxg,
                 const float* __restrict__ pw1,
                 const float* __restrict__ aP, const float* __restrict__ cP,
                 __half* __restrict__ hrelu)
{
    int r = blockIdx.x * 256 + threadIdx.x;
    int b = r >> 16;
    int n = (r >> 4) & (NN - 1);
    int j = idxg[r];
    float px = pos[((size_t)b * 3 + 0) * NN + n];
    float py = pos[((size_t)b * 3 + 1) * NN + n];
    float pz = pos[((size_t)b * 3 + 2) * NN + n];
    const float* sj = seed + ((size_t)b * MM + j) * 3;
    float rx = px - sj[0], ry = py - sj[1], rz = pz - sj[2];
    float ds = sqrtf(rx*rx + ry*ry + rz*rz);
    __half2* out = (__half2*)(hrelu + (size_t)r * PHD);
#pragma unroll
    for (int p0 = 0; p0 < PHD; p0 += 2) {
        float t[2];
#pragma unroll
        for (int u = 0; u < 2; u++) {
            int p = p0 + u;
            float raw = __ldg(&pw1[p*4]) * ds + __ldg(&pw1[p*4+1]) * rx
                      + __ldg(&pw1[p*4+2]) * ry + __ldg(&pw1[p*4+3]) * rz;
            t[u] = fmaxf(raw * __ldg(&aP[p]) + __ldg(&cP[p]), 0.f);
        }
        out[p0 >> 1] = __floats2half2_rn(t[0], t[1]);
    }
}

// ---------------- softmax over K + gather val + aggregate --------------------
__global__ __launch_bounds__(256)
void agg_kernel(const float* __restrict__ logits,
                const float* __restrict__ pe,
                const float* __restrict__ valft,
                const int*   __restrict__ idxg,
                float* __restrict__ agg)
{
    __shared__ int sj[KNB];
    int c = threadIdx.x;
    for (int pp = 0; pp < 16; pp++) {
        int pt = blockIdx.x * 16 + pp;
        int b = pt >> 12;
        size_t r0 = (size_t)pt * KNB;
        if (threadIdx.x < KNB) sj[threadIdx.x] = idxg[r0 + threadIdx.x];
        __syncthreads();
        float l[KNB];
        float m = -1e30f;
#pragma unroll
        for (int k = 0; k < KNB; k++) {
            l[k] = logits[(r0 + k) * DD + c];
            m = fmaxf(m, l[k]);
        }
        float S = 0.f, acc = 0.f;
#pragma unroll
        for (int k = 0; k < KNB; k++) {
            float ex = __expf(l[k] - m);
            S += ex;
            float v = valft[((size_t)b * MM + sj[k]) * DD + c];
            float p = pe[(r0 + k) * DD + c];
            acc += ex * (v + p);
        }
        agg[(size_t)pt * DD + c] = acc / S;
        __syncthreads();
    }
}

// ---------------- launch -----------------------------------------------------
extern "C" void kernel_launch(void* const* d_in, const int* in_sizes, int n_in,
                              void* d_out, int out_size)
{
    const float* pos      = (const float*)d_in[0];
    const float* pf       = (const float*)d_in[1];
    const float* fea      = (const float*)d_in[2];
    const float* seed     = (const float*)d_in[3];
    const float* seed_fea = (const float*)d_in[4];
    const float* w_start  = (const float*)d_in[5];
    const float* b_start  = (const float*)d_in[6];
    const float* w_key    = (const float*)d_in[7];
    const float* b_key    = (const float*)d_in[8];
    const float* w_value  = (const float*)d_in[9];
    const float* b_value  = (const float*)d_in[10];
    const float* w_query  = (const float*)d_in[11];
    const float* b_query  = (const float*)d_in[12];
    const float* pos_w1   = (const float*)d_in[13];
    const float* pos_b1   = (const float*)d_in[14];
    const float* pos_g1   = (const float*)d_in[15];
    const float* pos_beta1= (const float*)d_in[16];
    const float* pos_mu1  = (const float*)d_in[17];
    const float* pos_var1 = (const float*)d_in[18];
    const float* pos_w2   = (const float*)d_in[19];
    const float* pos_b2   = (const float*)d_in[20];
    const float* attn_w1  = (const float*)d_in[21];
    const float* attn_b1  = (const float*)d_in[22];
    const float* attn_g1  = (const float*)d_in[23];
    const float* attn_beta1=(const float*)d_in[24];
    const float* attn_mu1 = (const float*)d_in[25];
    const float* attn_var1= (const float*)d_in[26];
    const float* attn_w2  = (const float*)d_in[27];
    // d_in[28] = attn_b2: cancels in softmax over K
    const float* w_end    = (const float*)d_in[29];
    const float* b_end    = (const float*)d_in[30];

    float *valueT, *keyfT, *valftT, *queryT, *W1qt, *W1kt, *logits, *pe, *agg, *pre1;
    float *aA, *cA, *aP, *cP;
    __half *hrelu, *hid, *pre1h, *w1h, *w2h, *pw2h;
    int* idx;
    cudaGetSymbolAddress((void**)&valueT, g_valueT);
    cudaGetSymbolAddress((void**)&keyfT,  g_keyfT);
    cudaGetSymbolAddress((void**)&valftT, g_valftT);
    cudaGetSymbolAddress((void**)&queryT, g_queryT);
    cudaGetSymbolAddress((void**)&W1qt,   g_W1qt);
    cudaGetSymbolAddress((void**)&W1kt,   g_W1kt);
    cudaGetSymbolAddress((void**)&idx,    g_idx);
    cudaGetSymbolAddress((void**)&hrelu,  g_hrelu);
    cudaGetSymbolAddress((void**)&hid,    g_hid);
    cudaGetSymbolAddress((void**)&logits, g_logits);
    cudaGetSymbolAddress((void**)&pe,     g_pe);
    cudaGetSymbolAddress((void**)&agg,    g_agg);
    cudaGetSymbolAddress((void**)&pre1,   g_pre1);
    cudaGetSymbolAddress((void**)&pre1h,  g_pre1h);
    cudaGetSymbolAddress((void**)&w1h,    g_w1h);
    cudaGetSymbolAddress((void**)&w2h,    g_w2h);
    cudaGetSymbolAddress((void**)&pw2h,   g_pw2h);
    cudaGetSymbolAddress((void**)&aA,     g_aA);
    cudaGetSymbolAddress((void**)&cA,     g_cA);
    cudaGetSymbolAddress((void**)&aP,     g_aP);
    cudaGetSymbolAddress((void**)&cP,     g_cP);

    precomp_kernel<<<AHD + 1, PHD>>>(attn_w1, pos_w2, pos_b2,
                                     attn_g1, attn_beta1, attn_mu1, attn_var1, attn_b1,
                                     pos_g1, pos_beta1, pos_mu1, pos_var1, pos_b1,
                                     pre1, pre1h, aA, cA, aP, cP);
    cvt_h_kernel<<<(AHD*DD + 255)/256, 256>>>(attn_w1, w1h, AHD*DD);
    cvt_h_kernel<<<(DD*AHD + 255)/256, 256>>>(attn_w2, w2h, DD*AHD);
    cvt_h_kernel<<<(DD*PHD + 255)/256, 256>>>(pos_w2, pw2h, DD*PHD);

    // front GEMMs (SIMT fp32, row-major outputs)
    gemm_k<false,true><<<dim3(MM/128, DD/128, BB), 256>>>(
        w_start, b_start, seed_fea, nullptr, valueT, DD, CC, MM,
        (size_t)CC*MM, (size_t)MM*DD);
    gemm_k<true,true><<<dim3(MM/128, DD/128, BB), 256>>>(
        w_key, b_key, valueT, nullptr, keyfT, DD, DD, MM,
        (size_t)MM*DD, (size_t)MM*DD);
    gemm_k<true,true><<<dim3(MM/128, DD/128, BB), 256>>>(
        w_value, b_value, valueT, nullptr, valftT, DD, DD, MM,
        (size_t)MM*DD, (size_t)MM*DD);
    gemm_k<false,true><<<dim3(NN/128, DD/128, BB), 256>>>(
        w_query, b_query, fea, nullptr, queryT, DD, CC, NN,
        (size_t)CC*NN, (size_t)NN*DD);

    // W1q / W1k via fp16 mma (A staged fp32->fp16)
    hgemm<512,256,0,false,false><<<dim3(4, BB*NN/128), 256>>>(
        w1h, nullptr, queryT, W1qt, nullptr, nullptr, nullptr, nullptr, nullptr);
    hgemm<512,256,0,false,false><<<dim3(4, BB*MM/128), 256>>>(
        w1h, nullptr, keyfT, W1kt, nullptr, nullptr, nullptr, nullptr, nullptr);

    // knn + geometry
    knn_kernel<<<dim3(NN/4, BB), 128>>>(pf, seed, idx);
    geom_kernel<<<RR/256, 256>>>(pos, seed, idx, pos_w1, aP, cP, hrelu);

    // hid = relu(aA*(pre1@hrelu + W1q - W1k) + cA)  -> fp16
    hgemm<512,64,1,true,true><<<dim3(4, RR/128), 256>>>(
        pre1h, nullptr, hrelu, hid, W1qt, W1kt, idx, aA, cA);
    // logits = attn_w2 @ hid
    hgemm<256,512,0,true,false><<<dim3(2, RR/128), 256>>>(
        w2h, nullptr, hid, logits, nullptr, nullptr, nullptr, nullptr, nullptr);
    // pe = pos_w2 @ hrelu + pos_b2
    hgemm<256,64,0,true,false><<<dim3(2, RR/128), 256>>>(
        pw2h, pos_b2, hrelu, pe, nullptr, nullptr, nullptr, nullptr, nullptr);

    // softmax + gather + aggregate
    agg_kernel<<<BB*NN/16, 256>>>(logits, pe, valftT, idx, agg);
    // out = w_end @ agg + b_end + fea
    gemm_k<true,false><<<dim3(NN/128, CC/128, BB), 256>>>(
        w_end, b_end, agg, fea, (float*)d_out, CC, DD, NN,
        (size_t)NN*DD, (size_t)CC*NN);
}